// round 1
// baseline (speedup 1.0000x reference)
#include <cuda_runtime.h>
#include <math.h>

#define BATCH 4
#define SEQ 4096
#define DIM 512
#define QK 128
#define LN_EPS 1e-5f

// Scratch (allocation-free rule: __device__ globals)
__device__ float g_q[BATCH * SEQ * QK];
__device__ float g_k[BATCH * SEQ * QK];

// ---------------------------------------------------------------------------
// Kernel 1: fused LayerNorm + Linear(512->128) + SiLU + OffsetScale -> q, k
// One block handles 64 rows. 256 threads.
// ---------------------------------------------------------------------------
__global__ __launch_bounds__(256) void qk_kernel(
    const float* __restrict__ x,
    const float* __restrict__ lnw, const float* __restrict__ lnb,
    const float* __restrict__ w,   const float* __restrict__ bq,
    const float* __restrict__ gamma, const float* __restrict__ beta)
{
    __shared__ float s_mu[64], s_rs[64];
    __shared__ float At[32][68];    // [k-chunk][row], padded
    __shared__ float Wt[32][132];   // [k-chunk][out-ch], padded

    const int tid  = threadIdx.x;
    const int warp = tid >> 5, lane = tid & 31;
    const int row0 = blockIdx.x * 64;

    // --- LayerNorm stats: each warp does 8 rows ---
    for (int rr = 0; rr < 8; ++rr) {
        int r = warp * 8 + rr;
        const float* xr = x + (size_t)(row0 + r) * DIM;
        float s = 0.f, sq = 0.f;
#pragma unroll
        for (int i = 0; i < DIM / 32; ++i) {
            float v = xr[lane + 32 * i];
            s += v; sq += v * v;
        }
#pragma unroll
        for (int o = 16; o > 0; o >>= 1) {
            s  += __shfl_xor_sync(0xFFFFFFFFu, s,  o);
            sq += __shfl_xor_sync(0xFFFFFFFFu, sq, o);
        }
        if (lane == 0) {
            float mu  = s * (1.f / DIM);
            float var = sq * (1.f / DIM) - mu * mu;
            s_mu[r] = mu;
            s_rs[r] = rsqrtf(var + LN_EPS);
        }
    }
    __syncthreads();

    // --- GEMM: C[64x128] = normed[64x512] * W^T ---
    float acc[4][8];
#pragma unroll
    for (int i = 0; i < 4; ++i)
#pragma unroll
        for (int j = 0; j < 8; ++j) acc[i][j] = 0.f;

    const int ty = tid >> 4, tx = tid & 15;   // 16x16 thread grid
    const int c  = tid & 31, rb = tid >> 5;

    for (int kt = 0; kt < DIM; kt += 32) {
        float wlc = lnw[kt + c], blc = lnb[kt + c];
#pragma unroll
        for (int p = 0; p < 8; ++p) {
            int r = rb + p * 8;
            float xv = x[(size_t)(row0 + r) * DIM + kt + c];
            At[c][r] = (xv - s_mu[r]) * s_rs[r] * wlc + blc;
        }
#pragma unroll
        for (int p = 0; p < 16; ++p) {
            int e = rb + p * 8;
            Wt[c][e] = w[(size_t)e * DIM + kt + c];
        }
        __syncthreads();

#pragma unroll
        for (int c2 = 0; c2 < 32; ++c2) {
            float a[4], bb[8];
            *(float4*)a        = *(const float4*)&At[c2][ty * 4];
            *(float4*)bb       = *(const float4*)&Wt[c2][tx * 8];
            *(float4*)(bb + 4) = *(const float4*)&Wt[c2][tx * 8 + 4];
#pragma unroll
            for (int i = 0; i < 4; ++i)
#pragma unroll
                for (int j = 0; j < 8; ++j) acc[i][j] += a[i] * bb[j];
        }
        __syncthreads();
    }

    // --- Epilogue: +bias, SiLU, OffsetScale, store q & k ---
#pragma unroll
    for (int i = 0; i < 4; ++i) {
        int row = row0 + ty * 4 + i;
        float qv[8], kv[8];
#pragma unroll
        for (int j = 0; j < 8; ++j) {
            int e = tx * 8 + j;
            float z = acc[i][j] + bq[e];
            float v = z / (1.f + expf(-z));          // silu
            qv[j] = v * gamma[e]      + beta[e];
            kv[j] = v * gamma[QK + e] + beta[QK + e];
        }
        float* qp = g_q + (size_t)row * QK + tx * 8;
        float* kp = g_k + (size_t)row * QK + tx * 8;
        *(float4*)qp       = *(float4*)qv;
        *(float4*)(qp + 4) = *(float4*)(qv + 4);
        *(float4*)kp       = *(float4*)kv;
        *(float4*)(kp + 4) = *(float4*)(kv + 4);
    }
}

// ---------------------------------------------------------------------------
// Kernel 2: sim tile GEMM -> unnormalized relu(sim/64)^2 into out
// Tile 128x128, K=128 in chunks of 32. 256 threads, 8x8 per thread.
// ---------------------------------------------------------------------------
__global__ __launch_bounds__(256) void attn_kernel(float* __restrict__ out)
{
    __shared__ float Qs[32][132];   // [k][row-in-tile]
    __shared__ float Ks[32][132];   // [k][col-in-tile]

    const int b  = blockIdx.z;
    const int it = blockIdx.y;
    const int jt = blockIdx.x;

    const float* q = g_q + ((size_t)b * SEQ + it * 128) * QK;
    const float* k = g_k + ((size_t)b * SEQ + jt * 128) * QK;

    const int tid = threadIdx.x;
    const int ty = tid >> 4, tx = tid & 15;
    const int c  = tid & 31, rb = tid >> 5;

    float acc[8][8];
#pragma unroll
    for (int i = 0; i < 8; ++i)
#pragma unroll
        for (int j = 0; j < 8; ++j) acc[i][j] = 0.f;

    for (int kt = 0; kt < QK; kt += 32) {
#pragma unroll
        for (int p = 0; p < 16; ++p) {
            int r = rb + p * 8;
            Qs[c][r] = q[(size_t)r * QK + kt + c];
            Ks[c][r] = k[(size_t)r * QK + kt + c];
        }
        __syncthreads();

#pragma unroll
        for (int c2 = 0; c2 < 32; ++c2) {
            float a[8], bb[8];
            *(float4*)a        = *(const float4*)&Qs[c2][ty * 8];
            *(float4*)(a + 4)  = *(const float4*)&Qs[c2][ty * 8 + 4];
            *(float4*)bb       = *(const float4*)&Ks[c2][tx * 8];
            *(float4*)(bb + 4) = *(const float4*)&Ks[c2][tx * 8 + 4];
#pragma unroll
            for (int i = 0; i < 8; ++i)
#pragma unroll
                for (int j = 0; j < 8; ++j) acc[i][j] += a[i] * bb[j];
        }
        __syncthreads();
    }

    // Epilogue: scale by 1/64, relu, square, store (unnormalized)
#pragma unroll
    for (int i = 0; i < 8; ++i) {
        int irow = it * 128 + ty * 8 + i;
        float* op = out + ((size_t)b * SEQ + irow) * SEQ + jt * 128 + tx * 8;
        float v[8];
#pragma unroll
        for (int j = 0; j < 8; ++j) {
            float s = acc[i][j] * (1.f / 64.f);
            s = fmaxf(s, 0.f);
            v[j] = s * s;
        }
        *(float4*)op       = *(float4*)v;
        *(float4*)(op + 4) = *(float4*)(v + 4);
    }
}

// ---------------------------------------------------------------------------
// Kernel 3: per-row sum + in-place rescale. One block per row (deterministic).
// ---------------------------------------------------------------------------
__global__ __launch_bounds__(256) void norm_kernel(float* __restrict__ out)
{
    const size_t row = blockIdx.x;
    float4* p = (float4*)(out + row * SEQ);
    const int tid = threadIdx.x;

    float4 v[4];
    float s = 0.f;
#pragma unroll
    for (int i = 0; i < 4; ++i) {
        v[i] = p[tid + 256 * i];
        s += v[i].x + v[i].y + v[i].z + v[i].w;
    }

    __shared__ float red[256];
    red[tid] = s;
    __syncthreads();
#pragma unroll
    for (int o = 128; o > 0; o >>= 1) {
        if (tid < o) red[tid] += red[tid + o];
        __syncthreads();
    }
    float inv = 1.f / (red[0] + 1e-6f);

#pragma unroll
    for (int i = 0; i < 4; ++i) {
        v[i].x *= inv; v[i].y *= inv; v[i].z *= inv; v[i].w *= inv;
        p[tid + 256 * i] = v[i];
    }
}

// ---------------------------------------------------------------------------
extern "C" void kernel_launch(void* const* d_in, const int* in_sizes, int n_in,
                              void* d_out, int out_size)
{
    const float* x     = (const float*)d_in[0];
    const float* ln_w  = (const float*)d_in[1];
    const float* ln_b  = (const float*)d_in[2];
    const float* w_qk  = (const float*)d_in[3];
    const float* b_qk  = (const float*)d_in[4];
    const float* gamma = (const float*)d_in[5];
    const float* beta  = (const float*)d_in[6];
    float* out = (float*)d_out;

    qk_kernel<<<(BATCH * SEQ) / 64, 256>>>(x, ln_w, ln_b, w_qk, b_qk, gamma, beta);

    dim3 g2(SEQ / 128, SEQ / 128, BATCH);
    attn_kernel<<<g2, 256>>>(out);

    norm_kernel<<<BATCH * SEQ, 256>>>(out);
}

// round 3
// speedup vs baseline: 1.3074x; 1.3074x over previous
#include <cuda_runtime.h>
#include <cuda_bf16.h>
#include <cstdint>
#include <math.h>

#define BATCH 4
#define SEQ 4096
#define DIM 512
#define QK 128
#define LN_EPS 1e-5f

// bf16 hi/lo split scratch (allocation-free rule: __device__ globals)
__device__ __nv_bfloat16 g_qh[BATCH * SEQ * QK];
__device__ __nv_bfloat16 g_ql[BATCH * SEQ * QK];
__device__ __nv_bfloat16 g_kh[BATCH * SEQ * QK];
__device__ __nv_bfloat16 g_kl[BATCH * SEQ * QK];

// ---------------------------------------------------------------------------
// Kernel 1: fused LayerNorm + Linear(512->128) + SiLU + OffsetScale -> bf16 hi/lo
// 32 rows per block (grid 512) for better latency hiding.
// ---------------------------------------------------------------------------
__global__ __launch_bounds__(256) void qk_kernel(
    const float* __restrict__ x,
    const float* __restrict__ lnw, const float* __restrict__ lnb,
    const float* __restrict__ w,   const float* __restrict__ bq,
    const float* __restrict__ gamma, const float* __restrict__ beta)
{
    __shared__ float s_mu[32], s_rs[32];
    __shared__ float At[32][36];    // [k-chunk][row]
    __shared__ float Wt[32][132];   // [k-chunk][out-ch]

    const int tid  = threadIdx.x;
    const int warp = tid >> 5, lane = tid & 31;
    const int row0 = blockIdx.x * 32;

    // LayerNorm stats: each warp does 4 rows
#pragma unroll
    for (int rr = 0; rr < 4; ++rr) {
        int r = warp * 4 + rr;
        const float* xr = x + (size_t)(row0 + r) * DIM;
        float s = 0.f, sq = 0.f;
#pragma unroll
        for (int i = 0; i < DIM / 32; ++i) {
            float v = xr[lane + 32 * i];
            s += v; sq += v * v;
        }
#pragma unroll
        for (int o = 16; o > 0; o >>= 1) {
            s  += __shfl_xor_sync(0xFFFFFFFFu, s,  o);
            sq += __shfl_xor_sync(0xFFFFFFFFu, sq, o);
        }
        if (lane == 0) {
            float mu  = s * (1.f / DIM);
            float var = sq * (1.f / DIM) - mu * mu;
            s_mu[r] = mu;
            s_rs[r] = rsqrtf(var + LN_EPS);
        }
    }
    __syncthreads();

    float acc[2][8];
#pragma unroll
    for (int i = 0; i < 2; ++i)
#pragma unroll
        for (int j = 0; j < 8; ++j) acc[i][j] = 0.f;

    const int ty = tid >> 4, tx = tid & 15;
    const int c  = tid & 31, rb = tid >> 5;

    for (int kt = 0; kt < DIM; kt += 32) {
        float wlc = lnw[kt + c], blc = lnb[kt + c];
#pragma unroll
        for (int p = 0; p < 4; ++p) {
            int r = rb + p * 8;
            float xv = x[(size_t)(row0 + r) * DIM + kt + c];
            At[c][r] = (xv - s_mu[r]) * s_rs[r] * wlc + blc;
        }
#pragma unroll
        for (int p = 0; p < 16; ++p) {
            int e = rb + p * 8;
            Wt[c][e] = w[(size_t)e * DIM + kt + c];
        }
        __syncthreads();

#pragma unroll
        for (int c2 = 0; c2 < 32; ++c2) {
            float a[2], bb[8];
            *(float2*)a        = *(const float2*)&At[c2][ty * 2];
            *(float4*)bb       = *(const float4*)&Wt[c2][tx * 8];
            *(float4*)(bb + 4) = *(const float4*)&Wt[c2][tx * 8 + 4];
#pragma unroll
            for (int i = 0; i < 2; ++i)
#pragma unroll
                for (int j = 0; j < 8; ++j) acc[i][j] += a[i] * bb[j];
        }
        __syncthreads();
    }

#pragma unroll
    for (int i = 0; i < 2; ++i) {
        int row = row0 + ty * 2 + i;
        __nv_bfloat16 qh8[8], ql8[8], kh8[8], kl8[8];
#pragma unroll
        for (int j = 0; j < 8; ++j) {
            int e = tx * 8 + j;
            float z = acc[i][j] + bq[e];
            float v = z / (1.f + expf(-z));
            float qv = v * gamma[e]      + beta[e];
            float kv = v * gamma[QK + e] + beta[QK + e];
            qh8[j] = __float2bfloat16(qv);
            ql8[j] = __float2bfloat16(qv - __bfloat162float(qh8[j]));
            kh8[j] = __float2bfloat16(kv);
            kl8[j] = __float2bfloat16(kv - __bfloat162float(kh8[j]));
        }
        size_t off = (size_t)row * QK + tx * 8;
        *(uint4*)(g_qh + off) = *(uint4*)qh8;
        *(uint4*)(g_ql + off) = *(uint4*)ql8;
        *(uint4*)(g_kh + off) = *(uint4*)kh8;
        *(uint4*)(g_kl + off) = *(uint4*)kl8;
    }
}

// ---------------------------------------------------------------------------
// Kernel 2: bf16 hi/lo HMMA sim GEMM. CTA tile 128(m) x 64(n), K=128 one shot.
// smem: A hi/lo 64KB + B hi/lo 32KB = 96KB -> 2 CTAs/SM.
// ---------------------------------------------------------------------------
#define SA_HI 0
#define SA_LO 32768
#define SB_HI 65536
#define SB_LO 81920
#define ATT_SMEM 98304

__device__ __forceinline__ uint32_t smem_u32(const void* p) {
    uint32_t a;
    asm("{ .reg .u64 t; cvta.to.shared.u64 t, %1; cvt.u32.u64 %0, t; }" : "=r"(a) : "l"(p));
    return a;
}
__device__ __forceinline__ void cpasync16(uint32_t dst, const void* src) {
    asm volatile("cp.async.cg.shared.global [%0], [%1], 16;"
                 :: "r"(dst), "l"(__cvta_generic_to_global(src)));
}
__device__ __forceinline__ void ldsm4(uint32_t a, uint32_t& r0, uint32_t& r1,
                                      uint32_t& r2, uint32_t& r3) {
    asm volatile("ldmatrix.sync.aligned.m8n8.x4.shared.b16 {%0,%1,%2,%3}, [%4];"
                 : "=r"(r0), "=r"(r1), "=r"(r2), "=r"(r3) : "r"(a));
}
__device__ __forceinline__ void mma16816(float& c0, float& c1, float& c2, float& c3,
                                         uint32_t a0, uint32_t a1, uint32_t a2, uint32_t a3,
                                         uint32_t b0, uint32_t b1) {
    asm volatile("mma.sync.aligned.m16n8k16.row.col.f32.bf16.bf16.f32 "
                 "{%0,%1,%2,%3}, {%4,%5,%6,%7}, {%8,%9}, {%0,%1,%2,%3};"
                 : "+f"(c0), "+f"(c1), "+f"(c2), "+f"(c3)
                 : "r"(a0), "r"(a1), "r"(a2), "r"(a3), "r"(b0), "r"(b1));
}

// swizzled offset: row-major [rows][128 bf16], 16 chunks of 16B per row,
// physical chunk = chunk ^ (row & 7)
__device__ __forceinline__ uint32_t swoff(int r, int ch) {
    return (uint32_t)r * 256u + (uint32_t)((ch ^ (r & 7)) << 4);
}

__global__ __launch_bounds__(256, 2) void attn_kernel(float* __restrict__ out)
{
    extern __shared__ char smem[];
    const uint32_t sb = smem_u32(smem);
    const int tid = threadIdx.x, wid = tid >> 5, lane = tid & 31;
    const int b = blockIdx.z, it = blockIdx.y, jt = blockIdx.x;

    const size_t brow = (size_t)b * SEQ + it * 128;   // q rows base
    const size_t bcol = (size_t)b * SEQ + jt * 64;    // k rows base

    const __nv_bfloat16* qh = g_qh + brow * QK;
    const __nv_bfloat16* ql = g_ql + brow * QK;
    const __nv_bfloat16* kh = g_kh + bcol * QK;
    const __nv_bfloat16* kl = g_kl + bcol * QK;

    // --- load tiles (cp.async, swizzled) ---
#pragma unroll
    for (int i = 0; i < 8; ++i) {          // A: 128 rows x 16 chunks
        int idx = tid + 256 * i, r = idx >> 4, ch = idx & 15;
        cpasync16(sb + SA_HI + swoff(r, ch), qh + (size_t)r * QK + ch * 8);
        cpasync16(sb + SA_LO + swoff(r, ch), ql + (size_t)r * QK + ch * 8);
    }
#pragma unroll
    for (int i = 0; i < 4; ++i) {          // B: 64 rows x 16 chunks
        int idx = tid + 256 * i, r = idx >> 4, ch = idx & 15;
        cpasync16(sb + SB_HI + swoff(r, ch), kh + (size_t)r * QK + ch * 8);
        cpasync16(sb + SB_LO + swoff(r, ch), kl + (size_t)r * QK + ch * 8);
    }
    asm volatile("cp.async.commit_group;" ::: "memory");
    asm volatile("cp.async.wait_group 0;" ::: "memory");
    __syncthreads();

    // warp tiling: 4(m) x 2(n) warps; warp tile 32(m) x 32(n)
    const int wm0 = (wid & 3) * 32;
    const int wn0 = (wid >> 2) * 32;

    float acc[2][4][4];
#pragma unroll
    for (int mt = 0; mt < 2; ++mt)
#pragma unroll
        for (int n8 = 0; n8 < 4; ++n8)
#pragma unroll
            for (int v = 0; v < 4; ++v) acc[mt][n8][v] = 0.f;

    // precomputed per-lane row/col for ldmatrix
    const int a_r  = wm0 + (lane & 15);            // + mt*16
    const int a_cb = lane >> 4;                    // chunk low bit
    const int b_n  = wn0 + (lane & 7) + ((lane & 16) >> 1);  // + nb*16
    const int b_cb = (lane >> 3) & 1;

#pragma unroll
    for (int term = 0; term < 3; ++term) {
        const uint32_t sa = sb + ((term == 2) ? SA_LO : SA_HI);
        const uint32_t sB = sb + ((term == 1) ? SB_LO : SB_HI);
#pragma unroll
        for (int ks = 0; ks < 8; ++ks) {
            uint32_t a[2][4];
#pragma unroll
            for (int mt = 0; mt < 2; ++mt) {
                int r = a_r + mt * 16;
                ldsm4(sa + swoff(r, ks * 2 + a_cb), a[mt][0], a[mt][1], a[mt][2], a[mt][3]);
            }
            uint32_t bf[2][4];
#pragma unroll
            for (int nb = 0; nb < 2; ++nb) {
                int n = b_n + nb * 16;
                ldsm4(sB + swoff(n, ks * 2 + b_cb), bf[nb][0], bf[nb][1], bf[nb][2], bf[nb][3]);
            }
#pragma unroll
            for (int mt = 0; mt < 2; ++mt)
#pragma unroll
                for (int n8 = 0; n8 < 4; ++n8)
                    mma16816(acc[mt][n8][0], acc[mt][n8][1], acc[mt][n8][2], acc[mt][n8][3],
                             a[mt][0], a[mt][1], a[mt][2], a[mt][3],
                             bf[n8 >> 1][(n8 & 1) * 2], bf[n8 >> 1][(n8 & 1) * 2 + 1]);
        }
    }

    // --- epilogue: relu(sim/64)^2 unnormalized ---
#pragma unroll
    for (int mt = 0; mt < 2; ++mt) {
#pragma unroll
        for (int n8 = 0; n8 < 4; ++n8) {
            int grow = it * 128 + wm0 + mt * 16 + (lane >> 2);
            int gcol = jt * 64 + wn0 + n8 * 8 + (lane & 3) * 2;
            float* p0 = out + ((size_t)b * SEQ + grow) * SEQ + gcol;
            float* p1 = p0 + (size_t)8 * SEQ;
            float2 v0, v1;
            float s;
            s = fmaxf(acc[mt][n8][0] * 0.015625f, 0.f); v0.x = s * s;
            s = fmaxf(acc[mt][n8][1] * 0.015625f, 0.f); v0.y = s * s;
            s = fmaxf(acc[mt][n8][2] * 0.015625f, 0.f); v1.x = s * s;
            s = fmaxf(acc[mt][n8][3] * 0.015625f, 0.f); v1.y = s * s;
            *(float2*)p0 = v0;
            *(float2*)p1 = v1;
        }
    }
}

// ---------------------------------------------------------------------------
// Kernel 3: per-row sum + in-place rescale. One block per row.
// ---------------------------------------------------------------------------
__global__ __launch_bounds__(256) void norm_kernel(float* __restrict__ out)
{
    const size_t row = blockIdx.x;
    float4* p = (float4*)(out + row * SEQ);
    const int tid = threadIdx.x;

    float4 v[4];
    float s = 0.f;
#pragma unroll
    for (int i = 0; i < 4; ++i) {
        v[i] = p[tid + 256 * i];
        s += v[i].x + v[i].y + v[i].z + v[i].w;
    }

    __shared__ float red[256];
    red[tid] = s;
    __syncthreads();
#pragma unroll
    for (int o = 128; o > 0; o >>= 1) {
        if (tid < o) red[tid] += red[tid + o];
        __syncthreads();
    }
    float inv = 1.f / (red[0] + 1e-6f);

#pragma unroll
    for (int i = 0; i < 4; ++i) {
        v[i].x *= inv; v[i].y *= inv; v[i].z *= inv; v[i].w *= inv;
        p[tid + 256 * i] = v[i];
    }
}

// ---------------------------------------------------------------------------
extern "C" void kernel_launch(void* const* d_in, const int* in_sizes, int n_in,
                              void* d_out, int out_size)
{
    const float* x     = (const float*)d_in[0];
    const float* ln_w  = (const float*)d_in[1];
    const float* ln_b  = (const float*)d_in[2];
    const float* w_qk  = (const float*)d_in[3];
    const float* b_qk  = (const float*)d_in[4];
    const float* gamma = (const float*)d_in[5];
    const float* beta  = (const float*)d_in[6];
    float* out = (float*)d_out;

    qk_kernel<<<(BATCH * SEQ) / 32, 256>>>(x, ln_w, ln_b, w_qk, b_qk, gamma, beta);

    cudaFuncSetAttribute(attn_kernel, cudaFuncAttributeMaxDynamicSharedMemorySize, ATT_SMEM);
    dim3 g2(SEQ / 64, SEQ / 128, BATCH);
    attn_kernel<<<g2, 256, ATT_SMEM>>>(out);

    norm_kernel<<<BATCH * SEQ, 256>>>(out);
}

// round 4
// speedup vs baseline: 1.7086x; 1.3068x over previous
#include <cuda_runtime.h>
#include <cuda_bf16.h>
#include <cstdint>
#include <math.h>

#define BATCH 4
#define SEQ 4096
#define DIM 512
#define QK 128
#define LN_EPS 1e-5f
#define NJT 32

// bf16 hi/lo split scratch (allocation-free rule: __device__ globals)
__device__ __nv_bfloat16 g_qh[BATCH * SEQ * QK];
__device__ __nv_bfloat16 g_ql[BATCH * SEQ * QK];
__device__ __nv_bfloat16 g_kh[BATCH * SEQ * QK];
__device__ __nv_bfloat16 g_kl[BATCH * SEQ * QK];

// ---------------------------------------------------------------------------
// Kernel 1: fused LayerNorm + Linear(512->128) + SiLU + OffsetScale -> bf16 hi/lo
// 64 rows per block (the R1-measured-fast configuration).
// ---------------------------------------------------------------------------
__global__ __launch_bounds__(256) void qk_kernel(
    const float* __restrict__ x,
    const float* __restrict__ lnw, const float* __restrict__ lnb,
    const float* __restrict__ w,   const float* __restrict__ bq,
    const float* __restrict__ gamma, const float* __restrict__ beta)
{
    __shared__ float s_mu[64], s_rs[64];
    __shared__ float At[32][68];
    __shared__ float Wt[32][132];

    const int tid  = threadIdx.x;
    const int warp = tid >> 5, lane = tid & 31;
    const int row0 = blockIdx.x * 64;

    for (int rr = 0; rr < 8; ++rr) {
        int r = warp * 8 + rr;
        const float* xr = x + (size_t)(row0 + r) * DIM;
        float s = 0.f, sq = 0.f;
#pragma unroll
        for (int i = 0; i < DIM / 32; ++i) {
            float v = xr[lane + 32 * i];
            s += v; sq += v * v;
        }
#pragma unroll
        for (int o = 16; o > 0; o >>= 1) {
            s  += __shfl_xor_sync(0xFFFFFFFFu, s,  o);
            sq += __shfl_xor_sync(0xFFFFFFFFu, sq, o);
        }
        if (lane == 0) {
            float mu  = s * (1.f / DIM);
            float var = sq * (1.f / DIM) - mu * mu;
            s_mu[r] = mu;
            s_rs[r] = rsqrtf(var + LN_EPS);
        }
    }
    __syncthreads();

    float acc[4][8];
#pragma unroll
    for (int i = 0; i < 4; ++i)
#pragma unroll
        for (int j = 0; j < 8; ++j) acc[i][j] = 0.f;

    const int ty = tid >> 4, tx = tid & 15;
    const int c  = tid & 31, rb = tid >> 5;

    for (int kt = 0; kt < DIM; kt += 32) {
        float wlc = lnw[kt + c], blc = lnb[kt + c];
#pragma unroll
        for (int p = 0; p < 8; ++p) {
            int r = rb + p * 8;
            float xv = x[(size_t)(row0 + r) * DIM + kt + c];
            At[c][r] = (xv - s_mu[r]) * s_rs[r] * wlc + blc;
        }
#pragma unroll
        for (int p = 0; p < 16; ++p) {
            int e = rb + p * 8;
            Wt[c][e] = w[(size_t)e * DIM + kt + c];
        }
        __syncthreads();

#pragma unroll
        for (int c2 = 0; c2 < 32; ++c2) {
            float a[4], bb[8];
            *(float4*)a        = *(const float4*)&At[c2][ty * 4];
            *(float4*)bb       = *(const float4*)&Wt[c2][tx * 8];
            *(float4*)(bb + 4) = *(const float4*)&Wt[c2][tx * 8 + 4];
#pragma unroll
            for (int i = 0; i < 4; ++i)
#pragma unroll
                for (int j = 0; j < 8; ++j) acc[i][j] += a[i] * bb[j];
        }
        __syncthreads();
    }

#pragma unroll
    for (int i = 0; i < 4; ++i) {
        int row = row0 + ty * 4 + i;
        __nv_bfloat16 qh8[8], ql8[8], kh8[8], kl8[8];
#pragma unroll
        for (int j = 0; j < 8; ++j) {
            int e = tx * 8 + j;
            float z = acc[i][j] + bq[e];
            float v = z / (1.f + expf(-z));
            float qv = v * gamma[e]      + beta[e];
            float kv = v * gamma[QK + e] + beta[QK + e];
            qh8[j] = __float2bfloat16(qv);
            ql8[j] = __float2bfloat16(qv - __bfloat162float(qh8[j]));
            kh8[j] = __float2bfloat16(kv);
            kl8[j] = __float2bfloat16(kv - __bfloat162float(kh8[j]));
        }
        size_t off = (size_t)row * QK + tx * 8;
        *(uint4*)(g_qh + off) = *(uint4*)qh8;
        *(uint4*)(g_ql + off) = *(uint4*)ql8;
        *(uint4*)(g_kh + off) = *(uint4*)kh8;
        *(uint4*)(g_kl + off) = *(uint4*)kl8;
    }
}

// ---------------------------------------------------------------------------
// Kernel 2: strip-persistent bf16 hi/lo HMMA sim GEMM.
// CTA = 128 q-rows x full 4096 k-cols; B double-buffered via cp.async.
// smem: A hi/lo 64KB + 2 stages x (B hi/lo 64KB) = 192KB.
// ---------------------------------------------------------------------------
#define SA_HI 0
#define SA_LO 32768
#define SB0   65536          // stage s at + s*65536; lo at +32768
#define ATT_SMEM 196608

__device__ __forceinline__ uint32_t smem_u32(const void* p) {
    uint32_t a;
    asm("{ .reg .u64 t; cvta.to.shared.u64 t, %1; cvt.u32.u64 %0, t; }" : "=r"(a) : "l"(p));
    return a;
}
__device__ __forceinline__ void cpasync16(uint32_t dst, const void* src) {
    asm volatile("cp.async.cg.shared.global [%0], [%1], 16;"
                 :: "r"(dst), "l"(__cvta_generic_to_global(src)));
}
__device__ __forceinline__ void ldsm4(uint32_t a, uint32_t& r0, uint32_t& r1,
                                      uint32_t& r2, uint32_t& r3) {
    asm volatile("ldmatrix.sync.aligned.m8n8.x4.shared.b16 {%0,%1,%2,%3}, [%4];"
                 : "=r"(r0), "=r"(r1), "=r"(r2), "=r"(r3) : "r"(a));
}
__device__ __forceinline__ void mma16816(float* c,
                                         const uint32_t* a, uint32_t b0, uint32_t b1) {
    asm volatile("mma.sync.aligned.m16n8k16.row.col.f32.bf16.bf16.f32 "
                 "{%0,%1,%2,%3}, {%4,%5,%6,%7}, {%8,%9}, {%0,%1,%2,%3};"
                 : "+f"(c[0]), "+f"(c[1]), "+f"(c[2]), "+f"(c[3])
                 : "r"(a[0]), "r"(a[1]), "r"(a[2]), "r"(a[3]), "r"(b0), "r"(b1));
}
// swizzled offset: row stride 256B (128 bf16), 16 chunks of 16B, chunk ^= row&7
__device__ __forceinline__ uint32_t swoff(int r, int ch) {
    return (uint32_t)r * 256u + (uint32_t)((ch ^ (r & 7)) << 4);
}
// [128 rows x 128 bf16] gmem -> swizzled smem, 256 threads
__device__ __forceinline__ void load_tile128(uint32_t dst, const __nv_bfloat16* g, int tid) {
#pragma unroll
    for (int i = 0; i < 8; ++i) {
        int idx = tid + 256 * i;
        int r = idx >> 4, ch = idx & 15;
        cpasync16(dst + swoff(r, ch), g + (size_t)r * QK + ch * 8);
    }
}

__global__ __launch_bounds__(256, 1) void attn_kernel(float* __restrict__ out)
{
    extern __shared__ char smem[];
    const uint32_t sb = smem_u32(smem);
    const int tid = threadIdx.x, wid = tid >> 5, lane = tid & 31;
    const int b = blockIdx.y, strip = blockIdx.x;
    const size_t brow = (size_t)b * SEQ + strip * 128;

    const __nv_bfloat16* qh = g_qh + brow * QK;
    const __nv_bfloat16* ql = g_ql + brow * QK;
    const __nv_bfloat16* khb = g_kh + (size_t)b * SEQ * QK;
    const __nv_bfloat16* klb = g_kl + (size_t)b * SEQ * QK;

    // prologue: A + B stage0 (group0), B stage1 (group1)
    load_tile128(sb + SA_HI, qh, tid);
    load_tile128(sb + SA_LO, ql, tid);
    load_tile128(sb + SB0,         khb, tid);
    load_tile128(sb + SB0 + 32768, klb, tid);
    asm volatile("cp.async.commit_group;" ::: "memory");
    load_tile128(sb + SB0 + 65536,         khb + (size_t)128 * QK, tid);
    load_tile128(sb + SB0 + 65536 + 32768, klb + (size_t)128 * QK, tid);
    asm volatile("cp.async.commit_group;" ::: "memory");

    // warp tiling: 4(m) x 2(n); warp tile 32m x 64n
    const int wm0 = (wid & 3) * 32;
    const int wn0 = (wid >> 2) * 64;
    const int a_r  = wm0 + (lane & 15);
    const int a_cb = lane >> 4;
    const int b_n  = wn0 + (lane & 7) + ((lane & 16) >> 1);
    const int b_cb = (lane >> 3) & 1;

    for (int jt = 0; jt < NJT; ++jt) {
        const int s = jt & 1;
        asm volatile("cp.async.wait_group 1;" ::: "memory");
        __syncthreads();

        const uint32_t sBh = sb + SB0 + s * 65536;
        const uint32_t sBl = sBh + 32768;

        float acc[2][8][4];
#pragma unroll
        for (int mt = 0; mt < 2; ++mt)
#pragma unroll
            for (int n8 = 0; n8 < 8; ++n8)
#pragma unroll
                for (int v = 0; v < 4; ++v) acc[mt][n8][v] = 0.f;

#pragma unroll
        for (int ks = 0; ks < 8; ++ks) {
            uint32_t ah[2][4], al[2][4];
#pragma unroll
            for (int mt = 0; mt < 2; ++mt) {
                int r = a_r + mt * 16;
                ldsm4(sb + SA_HI + swoff(r, ks * 2 + a_cb), ah[mt][0], ah[mt][1], ah[mt][2], ah[mt][3]);
                ldsm4(sb + SA_LO + swoff(r, ks * 2 + a_cb), al[mt][0], al[mt][1], al[mt][2], al[mt][3]);
            }
            uint32_t bh[4][4], bl[4][4];
#pragma unroll
            for (int nb = 0; nb < 4; ++nb) {
                int n = b_n + nb * 16;
                ldsm4(sBh + swoff(n, ks * 2 + b_cb), bh[nb][0], bh[nb][1], bh[nb][2], bh[nb][3]);
                ldsm4(sBl + swoff(n, ks * 2 + b_cb), bl[nb][0], bl[nb][1], bl[nb][2], bl[nb][3]);
            }
#pragma unroll
            for (int mt = 0; mt < 2; ++mt)
#pragma unroll
                for (int n8 = 0; n8 < 8; ++n8) {
                    const int nb = n8 >> 1, hf = (n8 & 1) * 2;
                    mma16816(acc[mt][n8], ah[mt], bh[nb][hf], bh[nb][hf + 1]);
                    mma16816(acc[mt][n8], ah[mt], bl[nb][hf], bl[nb][hf + 1]);
                    mma16816(acc[mt][n8], al[mt], bh[nb][hf], bh[nb][hf + 1]);
                }
        }
        __syncthreads();   // all warps done with stage s

        // refill stage s with tile jt+2 (overlaps epilogue)
        if (jt + 2 < NJT) {
            load_tile128(sBh, khb + (size_t)(jt + 2) * 128 * QK, tid);
            load_tile128(sBl, klb + (size_t)(jt + 2) * 128 * QK, tid);
        }
        asm volatile("cp.async.commit_group;" ::: "memory");

        // epilogue: relu(sim/64)^2, unnormalized
#pragma unroll
        for (int mt = 0; mt < 2; ++mt) {
#pragma unroll
            for (int n8 = 0; n8 < 8; ++n8) {
                int grow = wm0 + mt * 16 + (lane >> 2);
                int gcol = jt * 128 + wn0 + n8 * 8 + (lane & 3) * 2;
                float* p0 = out + (brow + grow) * SEQ + gcol;
                float* p1 = p0 + (size_t)8 * SEQ;
                float s0, s1;
                float2 v0, v1;
                s0 = fmaxf(acc[mt][n8][0] * 0.015625f, 0.f); v0.x = s0 * s0;
                s1 = fmaxf(acc[mt][n8][1] * 0.015625f, 0.f); v0.y = s1 * s1;
                s0 = fmaxf(acc[mt][n8][2] * 0.015625f, 0.f); v1.x = s0 * s0;
                s1 = fmaxf(acc[mt][n8][3] * 0.015625f, 0.f); v1.y = s1 * s1;
                *(float2*)p0 = v0;
                *(float2*)p1 = v1;
            }
        }
    }
}

// ---------------------------------------------------------------------------
// Kernel 3: per-row sum + in-place rescale. One block per row.
// ---------------------------------------------------------------------------
__global__ __launch_bounds__(256) void norm_kernel(float* __restrict__ out)
{
    const size_t row = blockIdx.x;
    float4* p = (float4*)(out + row * SEQ);
    const int tid = threadIdx.x;

    float4 v[4];
    float s = 0.f;
#pragma unroll
    for (int i = 0; i < 4; ++i) {
        v[i] = p[tid + 256 * i];
        s += v[i].x + v[i].y + v[i].z + v[i].w;
    }

    __shared__ float red[256];
    red[tid] = s;
    __syncthreads();
#pragma unroll
    for (int o = 128; o > 0; o >>= 1) {
        if (tid < o) red[tid] += red[tid + o];
        __syncthreads();
    }
    float inv = 1.f / (red[0] + 1e-6f);

#pragma unroll
    for (int i = 0; i < 4; ++i) {
        v[i].x *= inv; v[i].y *= inv; v[i].z *= inv; v[i].w *= inv;
        p[tid + 256 * i] = v[i];
    }
}

// ---------------------------------------------------------------------------
extern "C" void kernel_launch(void* const* d_in, const int* in_sizes, int n_in,
                              void* d_out, int out_size)
{
    const float* x     = (const float*)d_in[0];
    const float* ln_w  = (const float*)d_in[1];
    const float* ln_b  = (const float*)d_in[2];
    const float* w_qk  = (const float*)d_in[3];
    const float* b_qk  = (const float*)d_in[4];
    const float* gamma = (const float*)d_in[5];
    const float* beta  = (const float*)d_in[6];
    float* out = (float*)d_out;

    qk_kernel<<<(BATCH * SEQ) / 64, 256>>>(x, ln_w, ln_b, w_qk, b_qk, gamma, beta);

    cudaFuncSetAttribute(attn_kernel, cudaFuncAttributeMaxDynamicSharedMemorySize, ATT_SMEM);
    dim3 g2(SEQ / 128, BATCH);
    attn_kernel<<<g2, 256, ATT_SMEM>>>(out);

    norm_kernel<<<BATCH * SEQ, 256>>>(out);
}

// round 6
// speedup vs baseline: 1.9792x; 1.1584x over previous
#include <cuda_runtime.h>
#include <cuda_bf16.h>
#include <cstdint>
#include <math.h>

#define BATCH 4
#define SEQ 4096
#define DIM 512
#define QK 128
#define LN_EPS 1e-5f
#define NJT 32

// bf16 hi/lo split scratch (allocation-free rule: __device__ globals)
__device__ __nv_bfloat16 g_qh[BATCH * SEQ * QK];
__device__ __nv_bfloat16 g_ql[BATCH * SEQ * QK];
__device__ __nv_bfloat16 g_kh[BATCH * SEQ * QK];
__device__ __nv_bfloat16 g_kl[BATCH * SEQ * QK];

// ---------------------------------------------------------------------------
// common helpers
// ---------------------------------------------------------------------------
__device__ __forceinline__ uint32_t smem_u32(const void* p) {
    uint32_t a;
    asm("{ .reg .u64 t; cvta.to.shared.u64 t, %1; cvt.u32.u64 %0, t; }" : "=r"(a) : "l"(p));
    return a;
}
__device__ __forceinline__ void cpasync16(uint32_t dst, const void* src) {
    asm volatile("cp.async.cg.shared.global [%0], [%1], 16;"
                 :: "r"(dst), "l"(__cvta_generic_to_global(src)));
}
__device__ __forceinline__ void ldsm4(uint32_t a, uint32_t& r0, uint32_t& r1,
                                      uint32_t& r2, uint32_t& r3) {
    asm volatile("ldmatrix.sync.aligned.m8n8.x4.shared.b16 {%0,%1,%2,%3}, [%4];"
                 : "=r"(r0), "=r"(r1), "=r"(r2), "=r"(r3) : "r"(a));
}
__device__ __forceinline__ void mma16816(float* c,
                                         const uint32_t* a, uint32_t b0, uint32_t b1) {
    asm volatile("mma.sync.aligned.m16n8k16.row.col.f32.bf16.bf16.f32 "
                 "{%0,%1,%2,%3}, {%4,%5,%6,%7}, {%8,%9}, {%0,%1,%2,%3};"
                 : "+f"(c[0]), "+f"(c[1]), "+f"(c[2]), "+f"(c[3])
                 : "r"(a[0]), "r"(a[1]), "r"(a[2]), "r"(a[3]), "r"(b0), "r"(b1));
}
// swizzled offset: row stride 256B (128 bf16), 16 chunks of 16B, chunk ^= row&7
__device__ __forceinline__ uint32_t swoff(int r, int ch) {
    return (uint32_t)r * 256u + (uint32_t)((ch ^ (r & 7)) << 4);
}

// ---------------------------------------------------------------------------
// Kernel 1 (tensorized): LayerNorm + Linear(512->128) + SiLU + OffsetScale.
// 128 CTAs x (128 rows, 128 out). K=512 in 4 chunks of 128.
// ---------------------------------------------------------------------------
#define QSA_HI 0
#define QSA_LO 32768
#define QSB_HI 65536
#define QSB_LO 98304
#define QST    131072
#define QK_SMEM (131072 + 1024)

__global__ __launch_bounds__(256, 1) void qk_kernel(
    const float* __restrict__ x,
    const float* __restrict__ lnw, const float* __restrict__ lnb,
    const float* __restrict__ w,   const float* __restrict__ bq,
    const float* __restrict__ gamma, const float* __restrict__ beta)
{
    extern __shared__ char sm[];
    const uint32_t sb = smem_u32(sm);
    float* s_mu = (float*)(sm + QST);
    float* s_rs = s_mu + 128;

    const int tid = threadIdx.x, wid = tid >> 5, lane = tid & 31;
    const int row0 = blockIdx.x * 128;

    // --- LN stats: each warp 16 rows ---
#pragma unroll 1
    for (int rr = 0; rr < 16; ++rr) {
        int r = wid * 16 + rr;
        const float4* xr = (const float4*)(x + (size_t)(row0 + r) * DIM);
        float s = 0.f, sq = 0.f;
#pragma unroll
        for (int i = 0; i < 4; ++i) {
            float4 v = xr[lane + 32 * i];
            s  += v.x + v.y + v.z + v.w;
            sq += v.x * v.x + v.y * v.y + v.z * v.z + v.w * v.w;
        }
#pragma unroll
        for (int o = 16; o > 0; o >>= 1) {
            s  += __shfl_xor_sync(0xFFFFFFFFu, s,  o);
            sq += __shfl_xor_sync(0xFFFFFFFFu, sq, o);
        }
        if (lane == 0) {
            float mu  = s * (1.f / DIM);
            float var = sq * (1.f / DIM) - mu * mu;
            s_mu[r] = mu;
            s_rs[r] = rsqrtf(var + LN_EPS);
        }
    }
    __syncthreads();

    // warp tiling: 4(m) x 2(n), warp tile 32m x 64n
    const int wm0 = (wid & 3) * 32;
    const int wn0 = (wid >> 2) * 64;
    const int a_r  = wm0 + (lane & 15);
    const int a_cb = lane >> 4;
    const int b_n  = wn0 + (lane & 7) + ((lane & 16) >> 1);
    const int b_cb = (lane >> 3) & 1;

    float acc[2][8][4];
#pragma unroll
    for (int mt = 0; mt < 2; ++mt)
#pragma unroll
        for (int n8 = 0; n8 < 8; ++n8)
#pragma unroll
            for (int v = 0; v < 4; ++v) acc[mt][n8][v] = 0.f;

    for (int c = 0; c < 4; ++c) {
        // --- stage A (normalized x) and B (W), hi/lo bf16, swizzled ---
        // FULL 128-row coverage: 8 iterations x 256 threads = 2048 (row,chunk) slots
#pragma unroll
        for (int i = 0; i < 8; ++i) {
            int idx = tid + 256 * i;
            int r = idx >> 4, ch = idx & 15;
            {
                float mu = s_mu[r], rs = s_rs[r];
                const float* xp = x + (size_t)(row0 + r) * DIM + c * 128 + ch * 8;
                const float* wl = lnw + c * 128 + ch * 8;
                const float* bl = lnb + c * 128 + ch * 8;
                __nv_bfloat16 h8[8], l8[8];
#pragma unroll
                for (int j = 0; j < 8; ++j) {
                    float v = (xp[j] - mu) * rs * wl[j] + bl[j];
                    h8[j] = __float2bfloat16(v);
                    l8[j] = __float2bfloat16(v - __bfloat162float(h8[j]));
                }
                *(uint4*)(sm + QSA_HI + swoff(r, ch)) = *(uint4*)h8;
                *(uint4*)(sm + QSA_LO + swoff(r, ch)) = *(uint4*)l8;
            }
            {
                const float* wp = w + (size_t)r * DIM + c * 128 + ch * 8;
                __nv_bfloat16 h8[8], l8[8];
#pragma unroll
                for (int j = 0; j < 8; ++j) {
                    float v = wp[j];
                    h8[j] = __float2bfloat16(v);
                    l8[j] = __float2bfloat16(v - __bfloat162float(h8[j]));
                }
                *(uint4*)(sm + QSB_HI + swoff(r, ch)) = *(uint4*)h8;
                *(uint4*)(sm + QSB_LO + swoff(r, ch)) = *(uint4*)l8;
            }
        }
        __syncthreads();

#pragma unroll
        for (int ks = 0; ks < 8; ++ks) {
            uint32_t ah[2][4], al[2][4];
#pragma unroll
            for (int mt = 0; mt < 2; ++mt) {
                int r = a_r + mt * 16;
                ldsm4(sb + QSA_HI + swoff(r, ks * 2 + a_cb), ah[mt][0], ah[mt][1], ah[mt][2], ah[mt][3]);
                ldsm4(sb + QSA_LO + swoff(r, ks * 2 + a_cb), al[mt][0], al[mt][1], al[mt][2], al[mt][3]);
            }
            uint32_t bh[4][4], bl[4][4];
#pragma unroll
            for (int nb = 0; nb < 4; ++nb) {
                int n = b_n + nb * 16;
                ldsm4(sb + QSB_HI + swoff(n, ks * 2 + b_cb), bh[nb][0], bh[nb][1], bh[nb][2], bh[nb][3]);
                ldsm4(sb + QSB_LO + swoff(n, ks * 2 + b_cb), bl[nb][0], bl[nb][1], bl[nb][2], bl[nb][3]);
            }
#pragma unroll
            for (int mt = 0; mt < 2; ++mt)
#pragma unroll
                for (int n8 = 0; n8 < 8; ++n8) {
                    const int nb = n8 >> 1, hf = (n8 & 1) * 2;
                    mma16816(acc[mt][n8], ah[mt], bh[nb][hf], bh[nb][hf + 1]);
                    mma16816(acc[mt][n8], ah[mt], bl[nb][hf], bl[nb][hf + 1]);
                    mma16816(acc[mt][n8], al[mt], bh[nb][hf], bh[nb][hf + 1]);
                }
        }
        __syncthreads();
    }

    // --- epilogue: bias + SiLU + OffsetScale -> bf16 hi/lo stores ---
#pragma unroll
    for (int n8 = 0; n8 < 8; ++n8) {
        int e0 = wn0 + n8 * 8 + (lane & 3) * 2;
        float bb0 = bq[e0],            bb1 = bq[e0 + 1];
        float g00 = gamma[e0],         g01 = gamma[e0 + 1];
        float b00 = beta[e0],          b01 = beta[e0 + 1];
        float g10 = gamma[QK + e0],    g11 = gamma[QK + e0 + 1];
        float b10 = beta[QK + e0],     b11 = beta[QK + e0 + 1];
#pragma unroll
        for (int mt = 0; mt < 2; ++mt) {
#pragma unroll
            for (int half = 0; half < 2; ++half) {
                int row = row0 + wm0 + mt * 16 + (lane >> 2) + half * 8;
                float z0 = acc[mt][n8][half * 2]     + bb0;
                float z1 = acc[mt][n8][half * 2 + 1] + bb1;
                float v0 = z0 / (1.f + expf(-z0));
                float v1 = z1 / (1.f + expf(-z1));
                float q0 = v0 * g00 + b00, q1 = v1 * g01 + b01;
                float k0 = v0 * g10 + b10, k1 = v1 * g11 + b11;
                __nv_bfloat16 t0, t1;
                size_t off = (size_t)row * QK + e0;
                t0 = __float2bfloat16(q0); t1 = __float2bfloat16(q1);
                *(uint32_t*)(g_qh + off) = (uint32_t)__bfloat16_as_ushort(t0) |
                                           ((uint32_t)__bfloat16_as_ushort(t1) << 16);
                __nv_bfloat16 r0 = __float2bfloat16(q0 - __bfloat162float(t0));
                __nv_bfloat16 r1 = __float2bfloat16(q1 - __bfloat162float(t1));
                *(uint32_t*)(g_ql + off) = (uint32_t)__bfloat16_as_ushort(r0) |
                                           ((uint32_t)__bfloat16_as_ushort(r1) << 16);
                t0 = __float2bfloat16(k0); t1 = __float2bfloat16(k1);
                *(uint32_t*)(g_kh + off) = (uint32_t)__bfloat16_as_ushort(t0) |
                                           ((uint32_t)__bfloat16_as_ushort(t1) << 16);
                r0 = __float2bfloat16(k0 - __bfloat162float(t0));
                r1 = __float2bfloat16(k1 - __bfloat162float(t1));
                *(uint32_t*)(g_kl + off) = (uint32_t)__bfloat16_as_ushort(r0) |
                                           ((uint32_t)__bfloat16_as_ushort(r1) << 16);
            }
        }
    }
}

// ---------------------------------------------------------------------------
// Kernel 2: strip-persistent bf16 hi/lo HMMA sim GEMM (unchanged from R4).
// ---------------------------------------------------------------------------
#define SA_HI 0
#define SA_LO 32768
#define SB0   65536
#define ATT_SMEM 196608

__device__ __forceinline__ void load_tile128(uint32_t dst, const __nv_bfloat16* g, int tid) {
#pragma unroll
    for (int i = 0; i < 8; ++i) {
        int idx = tid + 256 * i;
        int r = idx >> 4, ch = idx & 15;
        cpasync16(dst + swoff(r, ch), g + (size_t)r * QK + ch * 8);
    }
}

__global__ __launch_bounds__(256, 1) void attn_kernel(float* __restrict__ out)
{
    extern __shared__ char smem[];
    const uint32_t sb = smem_u32(smem);
    const int tid = threadIdx.x, wid = tid >> 5, lane = tid & 31;
    const int b = blockIdx.y, strip = blockIdx.x;
    const size_t brow = (size_t)b * SEQ + strip * 128;

    const __nv_bfloat16* qh = g_qh + brow * QK;
    const __nv_bfloat16* ql = g_ql + brow * QK;
    const __nv_bfloat16* khb = g_kh + (size_t)b * SEQ * QK;
    const __nv_bfloat16* klb = g_kl + (size_t)b * SEQ * QK;

    load_tile128(sb + SA_HI, qh, tid);
    load_tile128(sb + SA_LO, ql, tid);
    load_tile128(sb + SB0,         khb, tid);
    load_tile128(sb + SB0 + 32768, klb, tid);
    asm volatile("cp.async.commit_group;" ::: "memory");
    load_tile128(sb + SB0 + 65536,         khb + (size_t)128 * QK, tid);
    load_tile128(sb + SB0 + 65536 + 32768, klb + (size_t)128 * QK, tid);
    asm volatile("cp.async.commit_group;" ::: "memory");

    const int wm0 = (wid & 3) * 32;
    const int wn0 = (wid >> 2) * 64;
    const int a_r  = wm0 + (lane & 15);
    const int a_cb = lane >> 4;
    const int b_n  = wn0 + (lane & 7) + ((lane & 16) >> 1);
    const int b_cb = (lane >> 3) & 1;

    for (int jt = 0; jt < NJT; ++jt) {
        const int s = jt & 1;
        asm volatile("cp.async.wait_group 1;" ::: "memory");
        __syncthreads();

        const uint32_t sBh = sb + SB0 + s * 65536;
        const uint32_t sBl = sBh + 32768;

        float acc[2][8][4];
#pragma unroll
        for (int mt = 0; mt < 2; ++mt)
#pragma unroll
            for (int n8 = 0; n8 < 8; ++n8)
#pragma unroll
                for (int v = 0; v < 4; ++v) acc[mt][n8][v] = 0.f;

#pragma unroll
        for (int ks = 0; ks < 8; ++ks) {
            uint32_t ah[2][4], al[2][4];
#pragma unroll
            for (int mt = 0; mt < 2; ++mt) {
                int r = a_r + mt * 16;
                ldsm4(sb + SA_HI + swoff(r, ks * 2 + a_cb), ah[mt][0], ah[mt][1], ah[mt][2], ah[mt][3]);
                ldsm4(sb + SA_LO + swoff(r, ks * 2 + a_cb), al[mt][0], al[mt][1], al[mt][2], al[mt][3]);
            }
            uint32_t bh[4][4], bl[4][4];
#pragma unroll
            for (int nb = 0; nb < 4; ++nb) {
                int n = b_n + nb * 16;
                ldsm4(sBh + swoff(n, ks * 2 + b_cb), bh[nb][0], bh[nb][1], bh[nb][2], bh[nb][3]);
                ldsm4(sBl + swoff(n, ks * 2 + b_cb), bl[nb][0], bl[nb][1], bl[nb][2], bl[nb][3]);
            }
#pragma unroll
            for (int mt = 0; mt < 2; ++mt)
#pragma unroll
                for (int n8 = 0; n8 < 8; ++n8) {
                    const int nb = n8 >> 1, hf = (n8 & 1) * 2;
                    mma16816(acc[mt][n8], ah[mt], bh[nb][hf], bh[nb][hf + 1]);
                    mma16816(acc[mt][n8], ah[mt], bl[nb][hf], bl[nb][hf + 1]);
                    mma16816(acc[mt][n8], al[mt], bh[nb][hf], bh[nb][hf + 1]);
                }
        }
        __syncthreads();

        if (jt + 2 < NJT) {
            load_tile128(sBh, khb + (size_t)(jt + 2) * 128 * QK, tid);
            load_tile128(sBl, klb + (size_t)(jt + 2) * 128 * QK, tid);
        }
        asm volatile("cp.async.commit_group;" ::: "memory");

#pragma unroll
        for (int mt = 0; mt < 2; ++mt) {
#pragma unroll
            for (int n8 = 0; n8 < 8; ++n8) {
                int grow = wm0 + mt * 16 + (lane >> 2);
                int gcol = jt * 128 + wn0 + n8 * 8 + (lane & 3) * 2;
                float* p0 = out + (brow + grow) * SEQ + gcol;
                float* p1 = p0 + (size_t)8 * SEQ;
                float s0, s1;
                float2 v0, v1;
                s0 = fmaxf(acc[mt][n8][0] * 0.015625f, 0.f); v0.x = s0 * s0;
                s1 = fmaxf(acc[mt][n8][1] * 0.015625f, 0.f); v0.y = s1 * s1;
                s0 = fmaxf(acc[mt][n8][2] * 0.015625f, 0.f); v1.x = s0 * s0;
                s1 = fmaxf(acc[mt][n8][3] * 0.015625f, 0.f); v1.y = s1 * s1;
                *(float2*)p0 = v0;
                *(float2*)p1 = v1;
            }
        }
    }
}

// ---------------------------------------------------------------------------
// Kernel 3: per-row sum + in-place rescale.
// ---------------------------------------------------------------------------
__global__ __launch_bounds__(256) void norm_kernel(float* __restrict__ out)
{
    const size_t row = blockIdx.x;
    float4* p = (float4*)(out + row * SEQ);
    const int tid = threadIdx.x;

    float4 v[4];
    float s = 0.f;
#pragma unroll
    for (int i = 0; i < 4; ++i) {
        v[i] = p[tid + 256 * i];
        s += v[i].x + v[i].y + v[i].z + v[i].w;
    }

    __shared__ float red[256];
    red[tid] = s;
    __syncthreads();
#pragma unroll
    for (int o = 128; o > 0; o >>= 1) {
        if (tid < o) red[tid] += red[tid + o];
        __syncthreads();
    }
    float inv = 1.f / (red[0] + 1e-6f);

#pragma unroll
    for (int i = 0; i < 4; ++i) {
        v[i].x *= inv; v[i].y *= inv; v[i].z *= inv; v[i].w *= inv;
        p[tid + 256 * i] = v[i];
    }
}

// ---------------------------------------------------------------------------
extern "C" void kernel_launch(void* const* d_in, const int* in_sizes, int n_in,
                              void* d_out, int out_size)
{
    const float* x     = (const float*)d_in[0];
    const float* ln_w  = (const float*)d_in[1];
    const float* ln_b  = (const float*)d_in[2];
    const float* w_qk  = (const float*)d_in[3];
    const float* b_qk  = (const float*)d_in[4];
    const float* gamma = (const float*)d_in[5];
    const float* beta  = (const float*)d_in[6];
    float* out = (float*)d_out;

    cudaFuncSetAttribute(qk_kernel, cudaFuncAttributeMaxDynamicSharedMemorySize, QK_SMEM);
    qk_kernel<<<(BATCH * SEQ) / 128, 256, QK_SMEM>>>(x, ln_w, ln_b, w_qk, b_qk, gamma, beta);

    cudaFuncSetAttribute(attn_kernel, cudaFuncAttributeMaxDynamicSharedMemorySize, ATT_SMEM);
    dim3 g2(SEQ / 128, BATCH);
    attn_kernel<<<g2, 256, ATT_SMEM>>>(out);

    norm_kernel<<<BATCH * SEQ, 256>>>(out);
}